// round 1
// baseline (speedup 1.0000x reference)
#include <cuda_runtime.h>
#include <stdint.h>

#define NROWS  16384
#define NCODES 8192
#define KDIM   256
#define ZELEMS (NROWS * KDIM)          // 4194304

// ---------------- scratch (device globals; no runtime allocation) ----------
__device__ float g_scratch[(size_t)NROWS * NCODES]; // logits, reused in-place as W
__device__ float g_kl[NROWS];
__device__ float g_sse[1024];

// ---------------- threefry2x32, key = (0, 42) ------------------------------
__device__ __forceinline__ uint2 threefry2x32_k42(uint32_t x0, uint32_t x1) {
    const uint32_t ks0 = 0u;
    const uint32_t ks1 = 42u;
    const uint32_t ks2 = 0x1BD11BDAu ^ 0u ^ 42u;
    x0 += ks0; x1 += ks1;
#define TFR(r) { x0 += x1; x1 = (x1 << (r)) | (x1 >> (32 - (r))); x1 ^= x0; }
    TFR(13) TFR(15) TFR(26) TFR(6)
    x0 += ks1; x1 += ks2 + 1u;
    TFR(17) TFR(29) TFR(16) TFR(24)
    x0 += ks2; x1 += ks0 + 2u;
    TFR(13) TFR(15) TFR(26) TFR(6)
    x0 += ks0; x1 += ks1 + 3u;
    TFR(17) TFR(29) TFR(16) TFR(24)
    x0 += ks1; x1 += ks2 + 4u;
    TFR(13) TFR(15) TFR(26) TFR(6)
    x0 += ks2; x1 += ks0 + 5u;
#undef TFR
    return make_uint2(x0, x1);
}

// JAX partitionable path: flat index j -> bits = b1 ^ b2 of threefry(hi(j), lo(j))
__device__ __forceinline__ float gumbel_at(uint32_t j) {
    uint2 t = threefry2x32_k42(0u, j);
    uint32_t bits = t.x ^ t.y;
    // uniform(minval=tiny, maxval=1): f in [0,1), then max(tiny, f)
    float f = __uint_as_float((bits >> 9) | 0x3f800000u) - 1.0f;
    f = fmaxf(f, 1.17549435e-38f);
    return -logf(-logf(f));
}

// ---------------- block reduction helpers -----------------------------------
__device__ __forceinline__ float blockSum(float v, float* sc) {
    int lane = threadIdx.x & 31, w = threadIdx.x >> 5;
#pragma unroll
    for (int o = 16; o; o >>= 1) v += __shfl_xor_sync(0xffffffffu, v, o);
    if (lane == 0) sc[w] = v;
    __syncthreads();
    if (w == 0) {
        float x = (lane < 8) ? sc[lane] : 0.f;
#pragma unroll
        for (int o = 4; o; o >>= 1) x += __shfl_xor_sync(0xffffffffu, x, o);
        if (lane == 0) sc[0] = x;
    }
    __syncthreads();
    float r = sc[0];
    __syncthreads();
    return r;
}

__device__ __forceinline__ float blockMax(float v, float* sc) {
    int lane = threadIdx.x & 31, w = threadIdx.x >> 5;
#pragma unroll
    for (int o = 16; o; o >>= 1) v = fmaxf(v, __shfl_xor_sync(0xffffffffu, v, o));
    if (lane == 0) sc[w] = v;
    __syncthreads();
    if (w == 0) {
        float x = (lane < 8) ? sc[lane] : -3.4e38f;
#pragma unroll
        for (int o = 4; o; o >>= 1) x = fmaxf(x, __shfl_xor_sync(0xffffffffu, x, o));
        if (lane == 0) sc[0] = x;
    }
    __syncthreads();
    float r = sc[0];
    __syncthreads();
    return r;
}

// argmax with first-index tie-break; broadcasts result to all threads
__device__ __forceinline__ void blockArgmax(float& v, int& idx, float* scv, int* sci) {
    int lane = threadIdx.x & 31, w = threadIdx.x >> 5;
#pragma unroll
    for (int o = 16; o; o >>= 1) {
        float ov = __shfl_xor_sync(0xffffffffu, v, o);
        int   oi = __shfl_xor_sync(0xffffffffu, idx, o);
        if (ov > v || (ov == v && oi < idx)) { v = ov; idx = oi; }
    }
    if (lane == 0) { scv[w] = v; sci[w] = idx; }
    __syncthreads();
    if (w == 0) {
        float x = (lane < 8) ? scv[lane] : -3.4e38f;
        int   i = (lane < 8) ? sci[lane] : 0x7fffffff;
#pragma unroll
        for (int o = 4; o; o >>= 1) {
            float ov = __shfl_xor_sync(0xffffffffu, x, o);
            int   oi = __shfl_xor_sync(0xffffffffu, i, o);
            if (ov > x || (ov == x && oi < i)) { x = ov; i = oi; }
        }
        if (lane == 0) { scv[0] = x; sci[0] = i; }
    }
    __syncthreads();
    v = scv[0]; idx = sci[0];
    __syncthreads();
}

// ---------------- GEMM1: logits[M][N] = z[M][256] * codebook[N][256]^T -----
__global__ __launch_bounds__(256) void gemm_logits(const float* __restrict__ A,
                                                   const float* __restrict__ B) {
    const int BK = 32;
    __shared__ float As[BK][68];
    __shared__ float Bs[BK][68];
    int bx = blockIdx.x, by = blockIdx.y;
    int tid = threadIdx.x;
    int tx = tid & 15, ty = tid >> 4;
    float acc[4][4] = {};
    const float* Ab = A + (size_t)(by * 64) * KDIM;
    const float* Bb = B + (size_t)(bx * 64) * KDIM;

    for (int k0 = 0; k0 < KDIM; k0 += BK) {
#pragma unroll
        for (int r = 0; r < 2; r++) {
            int idx = tid + r * 256;        // 0..511
            int kg = idx & 7;               // 8 float4 groups over BK
            int m  = idx >> 3;              // 0..63
            float4 av = *(const float4*)(Ab + (size_t)m * KDIM + k0 + kg * 4);
            As[kg * 4 + 0][m] = av.x; As[kg * 4 + 1][m] = av.y;
            As[kg * 4 + 2][m] = av.z; As[kg * 4 + 3][m] = av.w;
            float4 bv = *(const float4*)(Bb + (size_t)m * KDIM + k0 + kg * 4);
            Bs[kg * 4 + 0][m] = bv.x; Bs[kg * 4 + 1][m] = bv.y;
            Bs[kg * 4 + 2][m] = bv.z; Bs[kg * 4 + 3][m] = bv.w;
        }
        __syncthreads();
#pragma unroll
        for (int k = 0; k < BK; k++) {
            float4 a = *(float4*)&As[k][ty * 4];
            float4 b = *(float4*)&Bs[k][tx * 4];
            acc[0][0] += a.x * b.x; acc[0][1] += a.x * b.y; acc[0][2] += a.x * b.z; acc[0][3] += a.x * b.w;
            acc[1][0] += a.y * b.x; acc[1][1] += a.y * b.y; acc[1][2] += a.y * b.z; acc[1][3] += a.y * b.w;
            acc[2][0] += a.z * b.x; acc[2][1] += a.z * b.y; acc[2][2] += a.z * b.z; acc[2][3] += a.z * b.w;
            acc[3][0] += a.w * b.x; acc[3][1] += a.w * b.y; acc[3][2] += a.w * b.z; acc[3][3] += a.w * b.w;
        }
        __syncthreads();
    }
#pragma unroll
    for (int i = 0; i < 4; i++) {
        size_t o = (size_t)(by * 64 + ty * 4 + i) * NCODES + bx * 64 + tx * 4;
        *(float4*)&g_scratch[o] = make_float4(acc[i][0], acc[i][1], acc[i][2], acc[i][3]);
    }
}

// ---------------- row ops: gumbel-softmax weights, KL, argmax ---------------
__global__ __launch_bounds__(256) void rowops(float* __restrict__ outCodes) {
    extern __shared__ float sm[];
    float* sl = sm;            // 8192 logits
    float* sy = sm + NCODES;   // 8192 logits+gumbel
    __shared__ float scv[8];
    __shared__ int   sci[8];

    int r = blockIdx.x;
    float* L = g_scratch + (size_t)r * NCODES;   // read logits, later write W in place

    float av = -3.4e38f; int ai = 0;
    float my = -3.4e38f;
    uint32_t jbase = (uint32_t)r * (uint32_t)NCODES;
    for (int c = threadIdx.x; c < NCODES; c += 256) {
        float a = L[c];
        float g = gumbel_at(jbase + (uint32_t)c);
        float ya = a + g;
        sl[c] = a; sy[c] = ya;
        if (a > av) { av = a; ai = c; }      // strictly greater -> first index kept
        my = fmaxf(my, ya);
    }
    __syncthreads();

    float ML = av; int code = ai;
    blockArgmax(ML, code, scv, sci);
    float MY = blockMax(my, scv);

    float sL = 0.f, sY = 0.f;
    for (int c = threadIdx.x; c < NCODES; c += 256) {
        sL += expf(sl[c] - ML);
        sY += expf(sy[c] - MY);
    }
    float SL = blockSum(sL, scv);
    float SY = blockSum(sY, scv);

    float kl = 0.f;
    float invSL = 1.f / SL, invSY = 1.f / SY;
    for (int c = threadIdx.x; c < NCODES; c += 256) {
        float p = expf(sl[c] - ML) * invSL;
        kl += p * logf(p * 8192.f + 1e-10f);
        L[c] = expf(sy[c] - MY) * invSY;     // overwrite logits row with W row
    }
    float KL = blockSum(kl, scv);

    if (threadIdx.x == 0) {
        g_kl[r] = KL;
        outCodes[r] = (float)code;
    }
}

// ---------------- GEMM2: z_q = W[M][8192] * codebook[8192][256], fused epi --
__global__ __launch_bounds__(256) void gemm_zq(const float* __restrict__ CB,
                                               const float* __restrict__ Z,
                                               float* __restrict__ OutZ) {
    const int BK = 32;
    __shared__ float As[BK][68];
    __shared__ float Bs[BK][68];
    __shared__ float sc[8];
    int bx = blockIdx.x, by = blockIdx.y;   // bx: 0..3 (D tiles), by: 0..255 (row tiles)
    int tid = threadIdx.x;
    int tx = tid & 15, ty = tid >> 4;
    float acc[4][4] = {};
    const float* Wb = g_scratch + (size_t)(by * 64) * NCODES;

    for (int k0 = 0; k0 < NCODES; k0 += BK) {
#pragma unroll
        for (int r = 0; r < 2; r++) {
            int idx = tid + r * 256;
            int kg = idx & 7;
            int m  = idx >> 3;
            float4 av = *(const float4*)(Wb + (size_t)m * NCODES + k0 + kg * 4);
            As[kg * 4 + 0][m] = av.x; As[kg * 4 + 1][m] = av.y;
            As[kg * 4 + 2][m] = av.z; As[kg * 4 + 3][m] = av.w;
            int n4 = idx & 15;
            int kk = idx >> 4;              // 0..31
            float4 bv = *(const float4*)(CB + (size_t)(k0 + kk) * KDIM + bx * 64 + n4 * 4);
            *(float4*)&Bs[kk][n4 * 4] = bv;
        }
        __syncthreads();
#pragma unroll
        for (int k = 0; k < BK; k++) {
            float4 a = *(float4*)&As[k][ty * 4];
            float4 b = *(float4*)&Bs[k][tx * 4];
            acc[0][0] += a.x * b.x; acc[0][1] += a.x * b.y; acc[0][2] += a.x * b.z; acc[0][3] += a.x * b.w;
            acc[1][0] += a.y * b.x; acc[1][1] += a.y * b.y; acc[1][2] += a.y * b.z; acc[1][3] += a.y * b.w;
            acc[2][0] += a.z * b.x; acc[2][1] += a.z * b.y; acc[2][2] += a.z * b.z; acc[2][3] += a.z * b.w;
            acc[3][0] += a.w * b.x; acc[3][1] += a.w * b.y; acc[3][2] += a.w * b.z; acc[3][3] += a.w * b.w;
        }
        __syncthreads();
    }

    // epilogue: z_q_st = z + (z_q - z); commit SSE partial
    float sse = 0.f;
#pragma unroll
    for (int i = 0; i < 4; i++) {
        size_t o = (size_t)(by * 64 + ty * 4 + i) * KDIM + bx * 64 + tx * 4;
        float4 zv = *(const float4*)(Z + o);
        float dx = acc[i][0] - zv.x, dy = acc[i][1] - zv.y;
        float dz = acc[i][2] - zv.z, dw = acc[i][3] - zv.w;
        sse += dx * dx + dy * dy + dz * dz + dw * dw;
        *(float4*)(OutZ + o) = make_float4(zv.x + dx, zv.y + dy, zv.z + dz, zv.w + dw);
    }
    float total = blockSum(sse, sc);
    if (tid == 0) g_sse[by * 4 + bx] = total;
}

// ---------------- finalize: total_loss -------------------------------------
__global__ __launch_bounds__(256) void finalize(float* __restrict__ outLoss) {
    __shared__ float sc[8];
    float k = 0.f;
    for (int i = threadIdx.x; i < NROWS; i += 256) k += g_kl[i];
    float K = blockSum(k, sc);
    float e = 0.f;
    for (int i = threadIdx.x; i < 1024; i += 256) e += g_sse[i];
    float E = blockSum(e, sc);
    if (threadIdx.x == 0)
        outLoss[0] = 0.25f * (E / (float)ZELEMS) + 0.01f * (K / (float)NROWS);
}

// ---------------- launch ----------------------------------------------------
extern "C" void kernel_launch(void* const* d_in, const int* in_sizes, int n_in,
                              void* d_out, int out_size) {
    const float* z  = (const float*)d_in[0];   // (8,64,32,256) -> 16384 x 256
    const float* cb = (const float*)d_in[1];   // 8192 x 256
    float* out = (float*)d_out;
    float* outZ     = out;                     // 4194304 floats
    float* outLoss  = out + ZELEMS;            // 1
    float* outCodes = out + ZELEMS + 1;        // 16384

    dim3 g1(NCODES / 64, NROWS / 64);
    gemm_logits<<<g1, 256>>>(z, cb);

    cudaFuncSetAttribute(rowops, cudaFuncAttributeMaxDynamicSharedMemorySize, 2 * NCODES * 4);
    rowops<<<NROWS, 256, 2 * NCODES * 4>>>(outCodes);

    dim3 g3(KDIM / 64, NROWS / 64);
    gemm_zq<<<g3, 256>>>(cb, z, outZ);

    finalize<<<1, 256>>>(outLoss);
}

// round 2
// speedup vs baseline: 1.0002x; 1.0002x over previous
#include <cuda_runtime.h>
#include <stdint.h>

#define NROWS  16384
#define NCODES 8192
#define KDIM   256
#define ZELEMS (NROWS * KDIM)          // 4194304

// ---------------- scratch (device globals; no runtime allocation) ----------
__device__ float g_scratch[(size_t)NROWS * NCODES]; // logits, reused in-place as W
__device__ float g_kl[NROWS];
__device__ float g_sse[1024];

// ---------------- threefry2x32, key = (0, 42) ------------------------------
__device__ __forceinline__ uint2 threefry2x32_k42(uint32_t x0, uint32_t x1) {
    const uint32_t ks0 = 0u;
    const uint32_t ks1 = 42u;
    const uint32_t ks2 = 0x1BD11BDAu ^ 0u ^ 42u;
    x0 += ks0; x1 += ks1;
#define TFR(r) { x0 += x1; x1 = (x1 << (r)) | (x1 >> (32 - (r))); x1 ^= x0; }
    TFR(13) TFR(15) TFR(26) TFR(6)
    x0 += ks1; x1 += ks2 + 1u;
    TFR(17) TFR(29) TFR(16) TFR(24)
    x0 += ks2; x1 += ks0 + 2u;
    TFR(13) TFR(15) TFR(26) TFR(6)
    x0 += ks0; x1 += ks1 + 3u;
    TFR(17) TFR(29) TFR(16) TFR(24)
    x0 += ks1; x1 += ks2 + 4u;
    TFR(13) TFR(15) TFR(26) TFR(6)
    x0 += ks2; x1 += ks0 + 5u;
#undef TFR
    return make_uint2(x0, x1);
}

// JAX partitionable path: flat index j -> bits = b1 ^ b2 of threefry(hi(j), lo(j))
__device__ __forceinline__ float gumbel_at(uint32_t j) {
    uint2 t = threefry2x32_k42(0u, j);
    uint32_t bits = t.x ^ t.y;
    // uniform(minval=tiny, maxval=1): f in [0,1), then max(tiny, f)
    float f = __uint_as_float((bits >> 9) | 0x3f800000u) - 1.0f;
    f = fmaxf(f, 1.17549435e-38f);
    return -logf(-logf(f));
}

// ---------------- block reduction helpers -----------------------------------
__device__ __forceinline__ float blockSum(float v, float* sc) {
    int lane = threadIdx.x & 31, w = threadIdx.x >> 5;
#pragma unroll
    for (int o = 16; o; o >>= 1) v += __shfl_xor_sync(0xffffffffu, v, o);
    if (lane == 0) sc[w] = v;
    __syncthreads();
    if (w == 0) {
        float x = (lane < 8) ? sc[lane] : 0.f;
#pragma unroll
        for (int o = 4; o; o >>= 1) x += __shfl_xor_sync(0xffffffffu, x, o);
        if (lane == 0) sc[0] = x;
    }
    __syncthreads();
    float r = sc[0];
    __syncthreads();
    return r;
}

__device__ __forceinline__ float blockMax(float v, float* sc) {
    int lane = threadIdx.x & 31, w = threadIdx.x >> 5;
#pragma unroll
    for (int o = 16; o; o >>= 1) v = fmaxf(v, __shfl_xor_sync(0xffffffffu, v, o));
    if (lane == 0) sc[w] = v;
    __syncthreads();
    if (w == 0) {
        float x = (lane < 8) ? sc[lane] : -3.4e38f;
#pragma unroll
        for (int o = 4; o; o >>= 1) x = fmaxf(x, __shfl_xor_sync(0xffffffffu, x, o));
        if (lane == 0) sc[0] = x;
    }
    __syncthreads();
    float r = sc[0];
    __syncthreads();
    return r;
}

// argmax with first-index tie-break; broadcasts result to all threads
__device__ __forceinline__ void blockArgmax(float& v, int& idx, float* scv, int* sci) {
    int lane = threadIdx.x & 31, w = threadIdx.x >> 5;
#pragma unroll
    for (int o = 16; o; o >>= 1) {
        float ov = __shfl_xor_sync(0xffffffffu, v, o);
        int   oi = __shfl_xor_sync(0xffffffffu, idx, o);
        if (ov > v || (ov == v && oi < idx)) { v = ov; idx = oi; }
    }
    if (lane == 0) { scv[w] = v; sci[w] = idx; }
    __syncthreads();
    if (w == 0) {
        float x = (lane < 8) ? scv[lane] : -3.4e38f;
        int   i = (lane < 8) ? sci[lane] : 0x7fffffff;
#pragma unroll
        for (int o = 4; o; o >>= 1) {
            float ov = __shfl_xor_sync(0xffffffffu, x, o);
            int   oi = __shfl_xor_sync(0xffffffffu, i, o);
            if (ov > x || (ov == x && oi < i)) { x = ov; i = oi; }
        }
        if (lane == 0) { scv[0] = x; sci[0] = i; }
    }
    __syncthreads();
    v = scv[0]; idx = sci[0];
    __syncthreads();
}

// ---------------- GEMM1: logits[M][N] = z[M][256] * codebook[N][256]^T -----
__global__ __launch_bounds__(256) void gemm_logits(const float* __restrict__ A,
                                                   const float* __restrict__ B) {
    const int BK = 32;
    __shared__ float As[BK][68];
    __shared__ float Bs[BK][68];
    int bx = blockIdx.x, by = blockIdx.y;
    int tid = threadIdx.x;
    int tx = tid & 15, ty = tid >> 4;
    float acc[4][4] = {};
    const float* Ab = A + (size_t)(by * 64) * KDIM;
    const float* Bb = B + (size_t)(bx * 64) * KDIM;

    for (int k0 = 0; k0 < KDIM; k0 += BK) {
#pragma unroll
        for (int r = 0; r < 2; r++) {
            int idx = tid + r * 256;        // 0..511
            int kg = idx & 7;               // 8 float4 groups over BK
            int m  = idx >> 3;              // 0..63
            float4 av = *(const float4*)(Ab + (size_t)m * KDIM + k0 + kg * 4);
            As[kg * 4 + 0][m] = av.x; As[kg * 4 + 1][m] = av.y;
            As[kg * 4 + 2][m] = av.z; As[kg * 4 + 3][m] = av.w;
            float4 bv = *(const float4*)(Bb + (size_t)m * KDIM + k0 + kg * 4);
            Bs[kg * 4 + 0][m] = bv.x; Bs[kg * 4 + 1][m] = bv.y;
            Bs[kg * 4 + 2][m] = bv.z; Bs[kg * 4 + 3][m] = bv.w;
        }
        __syncthreads();
#pragma unroll
        for (int k = 0; k < BK; k++) {
            float4 a = *(float4*)&As[k][ty * 4];
            float4 b = *(float4*)&Bs[k][tx * 4];
            acc[0][0] += a.x * b.x; acc[0][1] += a.x * b.y; acc[0][2] += a.x * b.z; acc[0][3] += a.x * b.w;
            acc[1][0] += a.y * b.x; acc[1][1] += a.y * b.y; acc[1][2] += a.y * b.z; acc[1][3] += a.y * b.w;
            acc[2][0] += a.z * b.x; acc[2][1] += a.z * b.y; acc[2][2] += a.z * b.z; acc[2][3] += a.z * b.w;
            acc[3][0] += a.w * b.x; acc[3][1] += a.w * b.y; acc[3][2] += a.w * b.z; acc[3][3] += a.w * b.w;
        }
        __syncthreads();
    }
#pragma unroll
    for (int i = 0; i < 4; i++) {
        size_t o = (size_t)(by * 64 + ty * 4 + i) * NCODES + bx * 64 + tx * 4;
        *(float4*)&g_scratch[o] = make_float4(acc[i][0], acc[i][1], acc[i][2], acc[i][3]);
    }
}

// ---------------- row ops: gumbel-softmax weights, KL, argmax ---------------
__global__ __launch_bounds__(256) void rowops(float* __restrict__ outCodes) {
    extern __shared__ float sm[];
    float* sl = sm;            // 8192 logits
    float* sy = sm + NCODES;   // 8192 logits+gumbel
    __shared__ float scv[8];
    __shared__ int   sci[8];

    int r = blockIdx.x;
    float* L = g_scratch + (size_t)r * NCODES;   // read logits, later write W in place

    float av = -3.4e38f; int ai = 0;
    float my = -3.4e38f;
    uint32_t jbase = (uint32_t)r * (uint32_t)NCODES;
    for (int c = threadIdx.x; c < NCODES; c += 256) {
        float a = L[c];
        float g = gumbel_at(jbase + (uint32_t)c);
        float ya = a + g;
        sl[c] = a; sy[c] = ya;
        if (a > av) { av = a; ai = c; }      // strictly greater -> first index kept
        my = fmaxf(my, ya);
    }
    __syncthreads();

    float ML = av; int code = ai;
    blockArgmax(ML, code, scv, sci);
    float MY = blockMax(my, scv);

    float sL = 0.f, sY = 0.f;
    for (int c = threadIdx.x; c < NCODES; c += 256) {
        sL += expf(sl[c] - ML);
        sY += expf(sy[c] - MY);
    }
    float SL = blockSum(sL, scv);
    float SY = blockSum(sY, scv);

    float kl = 0.f;
    float invSL = 1.f / SL, invSY = 1.f / SY;
    for (int c = threadIdx.x; c < NCODES; c += 256) {
        float p = expf(sl[c] - ML) * invSL;
        kl += p * logf(p * 8192.f + 1e-10f);
        L[c] = expf(sy[c] - MY) * invSY;     // overwrite logits row with W row
    }
    float KL = blockSum(kl, scv);

    if (threadIdx.x == 0) {
        g_kl[r] = KL;
        outCodes[r] = (float)code;
    }
}

// ---------------- GEMM2: z_q = W[M][8192] * codebook[8192][256], fused epi --
__global__ __launch_bounds__(256) void gemm_zq(const float* __restrict__ CB,
                                               const float* __restrict__ Z,
                                               float* __restrict__ OutZ) {
    const int BK = 32;
    __shared__ float As[BK][68];
    __shared__ float Bs[BK][68];
    __shared__ float sc[8];
    int bx = blockIdx.x, by = blockIdx.y;   // bx: 0..3 (D tiles), by: 0..255 (row tiles)
    int tid = threadIdx.x;
    int tx = tid & 15, ty = tid >> 4;
    float acc[4][4] = {};
    const float* Wb = g_scratch + (size_t)(by * 64) * NCODES;

    for (int k0 = 0; k0 < NCODES; k0 += BK) {
#pragma unroll
        for (int r = 0; r < 2; r++) {
            int idx = tid + r * 256;
            int kg = idx & 7;
            int m  = idx >> 3;
            float4 av = *(const float4*)(Wb + (size_t)m * NCODES + k0 + kg * 4);
            As[kg * 4 + 0][m] = av.x; As[kg * 4 + 1][m] = av.y;
            As[kg * 4 + 2][m] = av.z; As[kg * 4 + 3][m] = av.w;
            int n4 = idx & 15;
            int kk = idx >> 4;              // 0..31
            float4 bv = *(const float4*)(CB + (size_t)(k0 + kk) * KDIM + bx * 64 + n4 * 4);
            *(float4*)&Bs[kk][n4 * 4] = bv;
        }
        __syncthreads();
#pragma unroll
        for (int k = 0; k < BK; k++) {
            float4 a = *(float4*)&As[k][ty * 4];
            float4 b = *(float4*)&Bs[k][tx * 4];
            acc[0][0] += a.x * b.x; acc[0][1] += a.x * b.y; acc[0][2] += a.x * b.z; acc[0][3] += a.x * b.w;
            acc[1][0] += a.y * b.x; acc[1][1] += a.y * b.y; acc[1][2] += a.y * b.z; acc[1][3] += a.y * b.w;
            acc[2][0] += a.z * b.x; acc[2][1] += a.z * b.y; acc[2][2] += a.z * b.z; acc[2][3] += a.z * b.w;
            acc[3][0] += a.w * b.x; acc[3][1] += a.w * b.y; acc[3][2] += a.w * b.z; acc[3][3] += a.w * b.w;
        }
        __syncthreads();
    }

    // epilogue: z_q_st = z + (z_q - z); commit SSE partial
    float sse = 0.f;
#pragma unroll
    for (int i = 0; i < 4; i++) {
        size_t o = (size_t)(by * 64 + ty * 4 + i) * KDIM + bx * 64 + tx * 4;
        float4 zv = *(const float4*)(Z + o);
        float dx = acc[i][0] - zv.x, dy = acc[i][1] - zv.y;
        float dz = acc[i][2] - zv.z, dw = acc[i][3] - zv.w;
        sse += dx * dx + dy * dy + dz * dz + dw * dw;
        *(float4*)(OutZ + o) = make_float4(zv.x + dx, zv.y + dy, zv.z + dz, zv.w + dw);
    }
    float total = blockSum(sse, sc);
    if (tid == 0) g_sse[by * 4 + bx] = total;
}

// ---------------- finalize: total_loss -------------------------------------
__global__ __launch_bounds__(256) void finalize(float* __restrict__ outLoss) {
    __shared__ float sc[8];
    float k = 0.f;
    for (int i = threadIdx.x; i < NROWS; i += 256) k += g_kl[i];
    float K = blockSum(k, sc);
    float e = 0.f;
    for (int i = threadIdx.x; i < 1024; i += 256) e += g_sse[i];
    float E = blockSum(e, sc);
    if (threadIdx.x == 0)
        outLoss[0] = 0.25f * (E / (float)ZELEMS) + 0.01f * (K / (float)NROWS);
}

// ---------------- launch ----------------------------------------------------
extern "C" void kernel_launch(void* const* d_in, const int* in_sizes, int n_in,
                              void* d_out, int out_size) {
    const float* z  = (const float*)d_in[0];   // (8,64,32,256) -> 16384 x 256
    const float* cb = (const float*)d_in[1];   // 8192 x 256
    float* out = (float*)d_out;
    float* outZ     = out;                     // 4194304 floats
    float* outLoss  = out + ZELEMS;            // 1
    float* outCodes = out + ZELEMS + 1;        // 16384

    dim3 g1(NCODES / 64, NROWS / 64);
    gemm_logits<<<g1, 256>>>(z, cb);

    cudaFuncSetAttribute(rowops, cudaFuncAttributeMaxDynamicSharedMemorySize, 2 * NCODES * 4);
    rowops<<<NROWS, 256, 2 * NCODES * 4>>>(outCodes);

    dim3 g3(KDIM / 64, NROWS / 64);
    gemm_zq<<<g3, 256>>>(cb, z, outZ);

    finalize<<<1, 256>>>(outLoss);
}

// round 4
// speedup vs baseline: 1.2391x; 1.2388x over previous
#include <cuda_runtime.h>
#include <cuda_bf16.h>
#include <stdint.h>

#define NROWS  16384
#define NCODES 8192
#define KDIM   256
#define ZELEMS (NROWS * KDIM)

typedef __nv_bfloat16 bf16;

__device__ float g_logits[(size_t)NROWS * NCODES];
__device__ bf16  g_Whi[(size_t)NROWS * NCODES];
__device__ bf16  g_Wlo[(size_t)NROWS * NCODES];
__device__ bf16  g_Ahi[ZELEMS], g_Alo[ZELEMS];
__device__ bf16  g_Bhi[NCODES * KDIM], g_Blo[NCODES * KDIM];
__device__ bf16  g_CThi[(size_t)KDIM * NCODES], g_CTlo[(size_t)KDIM * NCODES];
__device__ float g_kl[NROWS];
__device__ float g_sse[256];

// ---------------- PTX helpers (all baseline sm_80-class, compute_103-safe) --
__device__ __forceinline__ uint32_t smem_u32(const void* p) {
    uint32_t a;
    asm("{ .reg .u64 t; cvta.to.shared.u64 t, %1; cvt.u32.u64 %0, t; }" : "=r"(a) : "l"(p));
    return a;
}
__device__ __forceinline__ void cp16(uint32_t dst, const void* src) {
    asm volatile("cp.async.cg.shared.global [%0], [%1], 16;\n" :: "r"(dst), "l"(src));
}
__device__ __forceinline__ void cp_commit() { asm volatile("cp.async.commit_group;\n" ::: "memory"); }
template<int N> __device__ __forceinline__ void cp_wait() {
    asm volatile("cp.async.wait_group %0;\n" :: "n"(N) : "memory");
}
__device__ __forceinline__ void ldsm4(uint32_t* r, uint32_t addr) {
    asm volatile("ldmatrix.sync.aligned.m8n8.x4.shared.b16 {%0,%1,%2,%3}, [%4];"
        : "=r"(r[0]), "=r"(r[1]), "=r"(r[2]), "=r"(r[3]) : "r"(addr));
}
__device__ __forceinline__ void ldsm2(uint32_t* r, uint32_t addr) {
    asm volatile("ldmatrix.sync.aligned.m8n8.x2.shared.b16 {%0,%1}, [%2];"
        : "=r"(r[0]), "=r"(r[1]) : "r"(addr));
}
__device__ __forceinline__ void mma16816(float* c, const uint32_t* a, const uint32_t* b) {
    asm volatile("mma.sync.aligned.m16n8k16.row.col.f32.bf16.bf16.f32 "
        "{%0,%1,%2,%3}, {%4,%5,%6,%7}, {%8,%9}, {%0,%1,%2,%3};"
        : "+f"(c[0]), "+f"(c[1]), "+f"(c[2]), "+f"(c[3])
        : "r"(a[0]), "r"(a[1]), "r"(a[2]), "r"(a[3]), "r"(b[0]), "r"(b[1]));
}

// ---------------- threefry2x32 key (0,42) + gumbel --------------------------
__device__ __forceinline__ uint2 tf2x32(uint32_t x0, uint32_t x1) {
    const uint32_t ks1 = 42u, ks2 = 0x1BD11BDAu ^ 42u;
    x1 += ks1;
#define TFR(r) { x0 += x1; x1 = (x1 << (r)) | (x1 >> (32 - (r))); x1 ^= x0; }
    TFR(13) TFR(15) TFR(26) TFR(6)
    x0 += ks1; x1 += ks2 + 1u;
    TFR(17) TFR(29) TFR(16) TFR(24)
    x0 += ks2; x1 += 2u;
    TFR(13) TFR(15) TFR(26) TFR(6)
    x1 += ks1 + 3u;
    TFR(17) TFR(29) TFR(16) TFR(24)
    x0 += ks1; x1 += ks2 + 4u;
    TFR(13) TFR(15) TFR(26) TFR(6)
    x0 += ks2; x1 += 5u;
#undef TFR
    return make_uint2(x0, x1);
}
__device__ __forceinline__ float gumbel_at(uint32_t j) {
    uint2 t = tf2x32(0u, j);
    uint32_t bits = t.x ^ t.y;
    float f = __uint_as_float((bits >> 9) | 0x3f800000u) - 1.0f;
    f = fmaxf(f, 1.17549435e-38f);
    float tt = f - 1.0f;                      // exact
    float inner;
    if (tt > -0.00390625f)
        inner = tt * (1.0f + tt * (-0.5f + tt * 0.33333333f));  // log1p series
    else
        inner = __logf(f);
    return -__logf(-inner);
}

// ---------------- reductions (256 threads) ----------------------------------
__device__ __forceinline__ float blockSum(float v, float* sc) {
    int lane = threadIdx.x & 31, w = threadIdx.x >> 5;
#pragma unroll
    for (int o = 16; o; o >>= 1) v += __shfl_xor_sync(0xffffffffu, v, o);
    if (lane == 0) sc[w] = v;
    __syncthreads();
    if (w == 0) {
        float x = (lane < 8) ? sc[lane] : 0.f;
#pragma unroll
        for (int o = 4; o; o >>= 1) x += __shfl_xor_sync(0xffffffffu, x, o);
        if (lane == 0) sc[0] = x;
    }
    __syncthreads();
    float r = sc[0];
    __syncthreads();
    return r;
}
__device__ __forceinline__ float blockMax(float v, float* sc) {
    int lane = threadIdx.x & 31, w = threadIdx.x >> 5;
#pragma unroll
    for (int o = 16; o; o >>= 1) v = fmaxf(v, __shfl_xor_sync(0xffffffffu, v, o));
    if (lane == 0) sc[w] = v;
    __syncthreads();
    if (w == 0) {
        float x = (lane < 8) ? sc[lane] : -3.4e38f;
#pragma unroll
        for (int o = 4; o; o >>= 1) x = fmaxf(x, __shfl_xor_sync(0xffffffffu, x, o));
        if (lane == 0) sc[0] = x;
    }
    __syncthreads();
    float r = sc[0];
    __syncthreads();
    return r;
}
__device__ __forceinline__ void blockArgmax(float& v, int& idx, float* scv, int* sci) {
    int lane = threadIdx.x & 31, w = threadIdx.x >> 5;
#pragma unroll
    for (int o = 16; o; o >>= 1) {
        float ov = __shfl_xor_sync(0xffffffffu, v, o);
        int   oi = __shfl_xor_sync(0xffffffffu, idx, o);
        if (ov > v || (ov == v && oi < idx)) { v = ov; idx = oi; }
    }
    if (lane == 0) { scv[w] = v; sci[w] = idx; }
    __syncthreads();
    if (w == 0) {
        float x = (lane < 8) ? scv[lane] : -3.4e38f;
        int   i = (lane < 8) ? sci[lane] : 0x7fffffff;
#pragma unroll
        for (int o = 4; o; o >>= 1) {
            float ov = __shfl_xor_sync(0xffffffffu, x, o);
            int   oi = __shfl_xor_sync(0xffffffffu, i, o);
            if (ov > x || (ov == x && oi < i)) { x = ov; i = oi; }
        }
        if (lane == 0) { scv[0] = x; sci[0] = i; }
    }
    __syncthreads();
    v = scv[0]; idx = sci[0];
    __syncthreads();
}

// ---------------- splitting kernels -----------------------------------------
__global__ __launch_bounds__(256) void split_z(const float* __restrict__ z) {
    int i = blockIdx.x * 256 + threadIdx.x;
    float x = z[i];
    bf16 h = __float2bfloat16(x);
    g_Ahi[i] = h;
    g_Alo[i] = __float2bfloat16(x - __bfloat162float(h));
}
__global__ __launch_bounds__(256) void split_cb(const float* __restrict__ cb) {
    int i = blockIdx.x * 256 + threadIdx.x;
    float x = cb[i];
    bf16 h = __float2bfloat16(x);
    g_Bhi[i] = h;
    g_Blo[i] = __float2bfloat16(x - __bfloat162float(h));
}
__global__ __launch_bounds__(256) void transpose_cb() {
    int i = blockIdx.x * 256 + threadIdx.x;     // d-major index
    int c = i & (NCODES - 1), d = i >> 13;
    g_CThi[i] = g_Bhi[c * KDIM + d];
    g_CTlo[i] = g_Blo[c * KDIM + d];
}

// ---------------- HMMA GEMM (MODE 0: logits, MODE 1: z_q) -------------------
// CTA 256 thr = 8 warps (2x4), tile M=128 N=128 BK=32; padded smem stride 40 bf16.
#define ASTR 40
#define TILE_ELEMS (128 * ASTR)

template<int MODE>
__global__ __launch_bounds__(256) void gemm_mma(const float* __restrict__ Z,
                                                float* __restrict__ Out) {
    __shared__ bf16 sA[2][TILE_ELEMS];
    __shared__ bf16 sB[2][TILE_ELEMS];
    __shared__ float ssum[8];

    int tid = threadIdx.x, lane = tid & 31, wid = tid >> 5;
    int wm = wid >> 2, wn = wid & 3;
    int m0 = blockIdx.y * 128, n0 = blockIdx.x * 128;

    const int NIT = (MODE == 0) ? 32 : 768;
    const int sAs = (MODE == 0) ? KDIM : NCODES;

    const bf16* At[4]; const bf16* Bt[4];
    if (MODE == 0) {
        At[0] = g_Ahi; At[1] = g_Alo; At[2] = g_Ahi; At[3] = g_Alo;
        Bt[0] = g_Bhi; Bt[1] = g_Bhi; Bt[2] = g_Blo; Bt[3] = g_Blo;
    } else {
        At[0] = g_Whi; At[1] = g_Wlo; At[2] = g_Whi; At[3] = g_Whi;
        Bt[0] = g_CThi; Bt[1] = g_CThi; Bt[2] = g_CTlo; Bt[3] = g_CTlo;
    }

    uint32_t sA0 = smem_u32(&sA[0][0]);
    uint32_t sB0 = smem_u32(&sB[0][0]);

    float acc[4][4][4] = {};

    auto load_stage = [&](int it, int s) {
        int term = (MODE == 0) ? (it >> 3) : (it >> 8);
        int k0   = (MODE == 0) ? ((it & 7) * 32) : ((it & 255) * 32);
        const bf16* A = At[term];
        const bf16* B = Bt[term];
        uint32_t da = sA0 + s * (TILE_ELEMS * 2);
        uint32_t db = sB0 + s * (TILE_ELEMS * 2);
#pragma unroll
        for (int i = 0; i < 2; i++) {
            int idx = tid + i * 256;            // 0..511
            int row = idx >> 2, ch = idx & 3;
            cp16(da + row * (ASTR * 2) + ch * 16, A + (size_t)(m0 + row) * sAs + k0 + ch * 8);
            cp16(db + row * (ASTR * 2) + ch * 16, B + (size_t)(n0 + row) * sAs + k0 + ch * 8);
        }
        cp_commit();
    };

    load_stage(0, 0);
    for (int it = 0; it < NIT; it++) {
        int s = it & 1;
        cp_wait<0>();
        __syncthreads();
        if (it + 1 < NIT) load_stage(it + 1, s ^ 1);

        uint32_t da = sA0 + s * (TILE_ELEMS * 2);
        uint32_t db = sB0 + s * (TILE_ELEMS * 2);
#pragma unroll
        for (int ks = 0; ks < 32; ks += 16) {
            uint32_t af[4][4], bfr[4][2];
#pragma unroll
            for (int mt = 0; mt < 4; mt++)
                ldsm4(af[mt], da + (uint32_t)((wm * 64 + mt * 16 + (lane & 15)) * (ASTR * 2)
                                              + (ks + ((lane >> 4) << 3)) * 2));
#pragma unroll
            for (int nt = 0; nt < 4; nt++)
                ldsm2(bfr[nt], db + (uint32_t)((wn * 32 + nt * 8 + (lane & 7)) * (ASTR * 2)
                                               + (ks + (((lane >> 3) & 1) << 3)) * 2));
#pragma unroll
            for (int mt = 0; mt < 4; mt++)
#pragma unroll
                for (int nt = 0; nt < 4; nt++)
                    mma16816(acc[mt][nt], af[mt], bfr[nt]);
        }
        __syncthreads();
    }

    // ---------------- epilogue ----------------
    int rbase = m0 + wm * 64 + (lane >> 2);
    int cbase = n0 + wn * 32 + (lane & 3) * 2;
    if (MODE == 0) {
#pragma unroll
        for (int mt = 0; mt < 4; mt++)
#pragma unroll
            for (int nt = 0; nt < 4; nt++) {
                int r0 = rbase + mt * 16, c0 = cbase + nt * 8;
                *(float2*)(g_logits + (size_t)r0 * NCODES + c0)       = make_float2(acc[mt][nt][0], acc[mt][nt][1]);
                *(float2*)(g_logits + (size_t)(r0 + 8) * NCODES + c0) = make_float2(acc[mt][nt][2], acc[mt][nt][3]);
            }
    } else {
        float sse = 0.f;
#pragma unroll
        for (int mt = 0; mt < 4; mt++)
#pragma unroll
            for (int nt = 0; nt < 4; nt++) {
                int r0 = rbase + mt * 16, c0 = cbase + nt * 8;
#pragma unroll
                for (int h = 0; h < 2; h++) {
                    size_t o = (size_t)(r0 + h * 8) * KDIM + c0;
                    float2 zv = *(const float2*)(Z + o);
                    float dx = acc[mt][nt][h * 2]     - zv.x;
                    float dy = acc[mt][nt][h * 2 + 1] - zv.y;
                    sse += dx * dx + dy * dy;
                    *(float2*)(Out + o) = make_float2(zv.x + dx, zv.y + dy);
                }
            }
#pragma unroll
        for (int o = 16; o; o >>= 1) sse += __shfl_xor_sync(0xffffffffu, sse, o);
        if (lane == 0) ssum[wid] = sse;
        __syncthreads();
        if (tid == 0) {
            float t = 0.f;
#pragma unroll
            for (int i = 0; i < 8; i++) t += ssum[i];
            g_sse[blockIdx.y * 2 + blockIdx.x] = t;
        }
    }
}

// ---------------- rowops ----------------------------------------------------
__global__ __launch_bounds__(256) void rowops(float* __restrict__ outCodes) {
    extern __shared__ float smf[];
    float* sl = smf;
    float* sy = smf + NCODES;
    __shared__ float scv[8];
    __shared__ int   sci[8];

    int r = blockIdx.x;
    const float* L = g_logits + (size_t)r * NCODES;

    float av = -3.4e38f; int ai = 0;
    float my = -3.4e38f;
    uint32_t jb = (uint32_t)r * (uint32_t)NCODES;
    for (int c = threadIdx.x; c < NCODES; c += 256) {
        float l = L[c];
        float g = gumbel_at(jb + (uint32_t)c);
        float y = l + g;
        sl[c] = l; sy[c] = y;
        if (l > av) { av = l; ai = c; }
        my = fmaxf(my, y);
    }
    __syncthreads();

    float ML = av; int code = ai;
    blockArgmax(ML, code, scv, sci);
    float MY = blockMax(my, scv);

    float sE = 0.f, sEl = 0.f, sEy = 0.f;
    for (int c = threadIdx.x; c < NCODES; c += 256) {
        float l = sl[c];
        float e = __expf(l - ML);
        sE += e; sEl += e * l;
        sEy += __expf(sy[c] - MY);
    }
    float SE  = blockSum(sE, scv);
    float SEl = blockSum(sEl, scv);
    float SY  = blockSum(sEy, scv);

    float inv = 1.0f / SY;
    bf16* wh = g_Whi + (size_t)r * NCODES;
    bf16* wl = g_Wlo + (size_t)r * NCODES;
    for (int c = threadIdx.x; c < NCODES; c += 256) {
        float w = __expf(sy[c] - MY) * inv;
        bf16 h = __float2bfloat16(w);
        wh[c] = h;
        wl[c] = __float2bfloat16(w - __bfloat162float(h));
    }
    if (threadIdx.x == 0) {
        g_kl[r] = SEl / SE - ML - __logf(SE) + 9.0109131f;   // + ln(8192)
        outCodes[r] = (float)code;
    }
}

// ---------------- finalize --------------------------------------------------
__global__ __launch_bounds__(256) void finalize(float* __restrict__ outLoss) {
    __shared__ float sc[8];
    float k = 0.f;
    for (int i = threadIdx.x; i < NROWS; i += 256) k += g_kl[i];
    float K = blockSum(k, sc);
    float e = g_sse[threadIdx.x];
    float E = blockSum(e, sc);
    if (threadIdx.x == 0)
        outLoss[0] = 0.25f * (E / (float)ZELEMS) + 0.01f * (K / (float)NROWS);
}

// ---------------- launch ----------------------------------------------------
extern "C" void kernel_launch(void* const* d_in, const int* in_sizes, int n_in,
                              void* d_out, int out_size) {
    const float* z  = (const float*)d_in[0];
    const float* cb = (const float*)d_in[1];
    float* out = (float*)d_out;
    float* outZ     = out;
    float* outLoss  = out + ZELEMS;
    float* outCodes = out + ZELEMS + 1;

    cudaFuncSetAttribute(rowops, cudaFuncAttributeMaxDynamicSharedMemorySize, 2 * NCODES * 4);

    split_z<<<ZELEMS / 256, 256>>>(z);
    split_cb<<<NCODES * KDIM / 256, 256>>>(cb);
    transpose_cb<<<NCODES * KDIM / 256, 256>>>();

    dim3 g1(NCODES / 128, NROWS / 128);          // (64, 128)
    gemm_mma<0><<<g1, 256>>>(nullptr, nullptr);

    rowops<<<NROWS, 256, 2 * NCODES * 4>>>(outCodes);

    dim3 g2(KDIM / 128, NROWS / 128);            // (2, 128)
    gemm_mma<1><<<g2, 256>>>(z, outZ);

    finalize<<<1, 256>>>(outLoss);
}

// round 5
// speedup vs baseline: 2.3339x; 1.8835x over previous
#include <cuda_runtime.h>
#include <cuda_fp16.h>
#include <stdint.h>

#define NROWS  16384
#define NCODES 8192
#define KDIM   256
#define ZELEMS (NROWS * KDIM)

typedef __half fp16;

__device__ float g_logits[(size_t)NROWS * NCODES];
__device__ fp16  g_Whi[(size_t)NROWS * NCODES];
__device__ fp16  g_Wlo[(size_t)NROWS * NCODES];
__device__ fp16  g_Ahi[ZELEMS], g_Alo[ZELEMS];
__device__ fp16  g_Bhi[NCODES * KDIM], g_Blo[NCODES * KDIM];
__device__ fp16  g_CThi[(size_t)KDIM * NCODES], g_CTlo[(size_t)KDIM * NCODES];
__device__ float g_kl[NROWS];
__device__ float g_sse[256];

// ---------------- PTX helpers (baseline, compute_103-safe) ------------------
__device__ __forceinline__ uint32_t smem_u32(const void* p) {
    uint32_t a;
    asm("{ .reg .u64 t; cvta.to.shared.u64 t, %1; cvt.u32.u64 %0, t; }" : "=r"(a) : "l"(p));
    return a;
}
__device__ __forceinline__ void cp16(uint32_t dst, const void* src) {
    asm volatile("cp.async.cg.shared.global [%0], [%1], 16;\n" :: "r"(dst), "l"(src));
}
__device__ __forceinline__ void cp_commit() { asm volatile("cp.async.commit_group;\n" ::: "memory"); }
template<int N> __device__ __forceinline__ void cp_wait() {
    asm volatile("cp.async.wait_group %0;\n" :: "n"(N) : "memory");
}
__device__ __forceinline__ void ldsm4(uint32_t* r, uint32_t addr) {
    asm volatile("ldmatrix.sync.aligned.m8n8.x4.shared.b16 {%0,%1,%2,%3}, [%4];"
        : "=r"(r[0]), "=r"(r[1]), "=r"(r[2]), "=r"(r[3]) : "r"(addr));
}
__device__ __forceinline__ void mma16816(float* c, const uint32_t* a, const uint32_t* b) {
    asm volatile("mma.sync.aligned.m16n8k16.row.col.f32.f16.f16.f32 "
        "{%0,%1,%2,%3}, {%4,%5,%6,%7}, {%8,%9}, {%0,%1,%2,%3};"
        : "+f"(c[0]), "+f"(c[1]), "+f"(c[2]), "+f"(c[3])
        : "r"(a[0]), "r"(a[1]), "r"(a[2]), "r"(a[3]), "r"(b[0]), "r"(b[1]));
}

// ---------------- threefry2x32 key (0,42) + gumbel --------------------------
__device__ __forceinline__ uint2 tf2x32(uint32_t x0, uint32_t x1) {
    const uint32_t ks1 = 42u, ks2 = 0x1BD11BDAu ^ 42u;
    x1 += ks1;
#define TFR(r) { x0 += x1; x1 = (x1 << (r)) | (x1 >> (32 - (r))); x1 ^= x0; }
    TFR(13) TFR(15) TFR(26) TFR(6)
    x0 += ks1; x1 += ks2 + 1u;
    TFR(17) TFR(29) TFR(16) TFR(24)
    x0 += ks2; x1 += 2u;
    TFR(13) TFR(15) TFR(26) TFR(6)
    x1 += ks1 + 3u;
    TFR(17) TFR(29) TFR(16) TFR(24)
    x0 += ks1; x1 += ks2 + 4u;
    TFR(13) TFR(15) TFR(26) TFR(6)
    x0 += ks2; x1 += 5u;
#undef TFR
    return make_uint2(x0, x1);
}
__device__ __forceinline__ float gumbel_at(uint32_t j) {
    uint2 t = tf2x32(0u, j);
    uint32_t bits = t.x ^ t.y;
    float f = __uint_as_float((bits >> 9) | 0x3f800000u) - 1.0f;
    f = fmaxf(f, 1.17549435e-38f);
    float tt = f - 1.0f;                       // exact
    float inner;
    if (tt > -0.00390625f)
        inner = tt * (1.0f + tt * (-0.5f + tt * 0.33333333f));
    else
        inner = __logf(f);
    return -__logf(-inner);
}

// ---------------- reductions (256 threads) ----------------------------------
__device__ __forceinline__ float blockSum(float v, float* sc) {
    int lane = threadIdx.x & 31, w = threadIdx.x >> 5;
#pragma unroll
    for (int o = 16; o; o >>= 1) v += __shfl_xor_sync(0xffffffffu, v, o);
    if (lane == 0) sc[w] = v;
    __syncthreads();
    if (w == 0) {
        float x = (lane < 8) ? sc[lane] : 0.f;
#pragma unroll
        for (int o = 4; o; o >>= 1) x += __shfl_xor_sync(0xffffffffu, x, o);
        if (lane == 0) sc[0] = x;
    }
    __syncthreads();
    float r = sc[0];
    __syncthreads();
    return r;
}
__device__ __forceinline__ float blockMax(float v, float* sc) {
    int lane = threadIdx.x & 31, w = threadIdx.x >> 5;
#pragma unroll
    for (int o = 16; o; o >>= 1) v = fmaxf(v, __shfl_xor_sync(0xffffffffu, v, o));
    if (lane == 0) sc[w] = v;
    __syncthreads();
    if (w == 0) {
        float x = (lane < 8) ? sc[lane] : -3.4e38f;
#pragma unroll
        for (int o = 4; o; o >>= 1) x = fmaxf(x, __shfl_xor_sync(0xffffffffu, x, o));
        if (lane == 0) sc[0] = x;
    }
    __syncthreads();
    float r = sc[0];
    __syncthreads();
    return r;
}
__device__ __forceinline__ void blockArgmax(float& v, int& idx, float* scv, int* sci) {
    int lane = threadIdx.x & 31, w = threadIdx.x >> 5;
#pragma unroll
    for (int o = 16; o; o >>= 1) {
        float ov = __shfl_xor_sync(0xffffffffu, v, o);
        int   oi = __shfl_xor_sync(0xffffffffu, idx, o);
        if (ov > v || (ov == v && oi < idx)) { v = ov; idx = oi; }
    }
    if (lane == 0) { scv[w] = v; sci[w] = idx; }
    __syncthreads();
    if (w == 0) {
        float x = (lane < 8) ? scv[lane] : -3.4e38f;
        int   i = (lane < 8) ? sci[lane] : 0x7fffffff;
#pragma unroll
        for (int o = 4; o; o >>= 1) {
            float ov = __shfl_xor_sync(0xffffffffu, x, o);
            int   oi = __shfl_xor_sync(0xffffffffu, i, o);
            if (ov > x || (ov == x && oi < i)) { x = ov; i = oi; }
        }
        if (lane == 0) { scv[0] = x; sci[0] = i; }
    }
    __syncthreads();
    v = scv[0]; idx = sci[0];
    __syncthreads();
}

// ---------------- split kernels ---------------------------------------------
__global__ __launch_bounds__(256) void split_z(const float* __restrict__ z) {
    int i = blockIdx.x * 256 + threadIdx.x;
    float x = z[i];
    fp16 h = __float2half_rn(x);
    g_Ahi[i] = h;
    g_Alo[i] = __float2half_rn(x - __half2float(h));
}
// split + tiled transpose of codebook: writes Bhi/Blo (row-major) + CThi/CTlo (transposed)
__global__ __launch_bounds__(256) void split_cb(const float* __restrict__ cb) {
    __shared__ fp16 th[64][65], tl[64][65];
    int bc = blockIdx.x * 64, bd = blockIdx.y * 64;
    int t = threadIdx.x;
#pragma unroll 4
    for (int cc = 0; cc < 16; cc++) {
        int c = (t >> 6) * 16 + cc;
        int d = t & 63;
        size_t gi = (size_t)(bc + c) * KDIM + bd + d;
        float x = cb[gi];
        fp16 h = __float2half_rn(x);
        fp16 l = __float2half_rn(x - __half2float(h));
        g_Bhi[gi] = h; g_Blo[gi] = l;
        th[c][d] = h; tl[c][d] = l;
    }
    __syncthreads();
#pragma unroll 4
    for (int dd = 0; dd < 16; dd++) {
        int d = (t >> 6) * 16 + dd;
        int c = t & 63;
        size_t gi = (size_t)(bd + d) * NCODES + bc + c;
        g_CThi[gi] = th[c][d];
        g_CTlo[gi] = tl[c][d];
    }
}

// ---------------- HMMA GEMM: 128x128 CTA, 4 warps of 64x64, BK=32 -----------
#define ASTR 40
#define TILE_B (128 * ASTR * 2)

template<int MODE>
__global__ __launch_bounds__(128) void gemm_mma(const float* __restrict__ Z,
                                                float* __restrict__ Out) {
    __shared__ fp16 sA[2][128 * ASTR];
    __shared__ fp16 sB[2][128 * ASTR];
    __shared__ float ssum[4];

    int tid = threadIdx.x, lane = tid & 31, wid = tid >> 5;
    int wm = wid >> 1, wn = wid & 1;
    int m0 = blockIdx.y * 128, n0 = blockIdx.x * 128;

    const int NIT = (MODE == 0) ? 24 : 768;
    const int sAs = (MODE == 0) ? KDIM : NCODES;

    const fp16* At[3]; const fp16* Bt[3];
    if (MODE == 0) {
        At[0] = g_Ahi; At[1] = g_Alo; At[2] = g_Ahi;
        Bt[0] = g_Bhi; Bt[1] = g_Bhi; Bt[2] = g_Blo;
    } else {
        At[0] = g_Whi; At[1] = g_Wlo; At[2] = g_Whi;
        Bt[0] = g_CThi; Bt[1] = g_CThi; Bt[2] = g_CTlo;
    }

    uint32_t sA0 = smem_u32(&sA[0][0]);
    uint32_t sB0 = smem_u32(&sB[0][0]);

    float acc[4][8][4] = {};

    auto load_stage = [&](int it, int s) {
        int term = (MODE == 0) ? (it >> 3) : (it >> 8);
        int k0   = (MODE == 0) ? ((it & 7) * 32) : ((it & 255) * 32);
        const fp16* A = At[term];
        const fp16* B = Bt[term];
        uint32_t da = sA0 + s * TILE_B;
        uint32_t db = sB0 + s * TILE_B;
#pragma unroll
        for (int i = 0; i < 4; i++) {
            int idx = tid + i * 128;           // 0..511
            int row = idx >> 2, ch = idx & 3;
            cp16(da + row * 80 + ch * 16, A + (size_t)(m0 + row) * sAs + k0 + ch * 8);
            cp16(db + row * 80 + ch * 16, B + (size_t)(n0 + row) * sAs + k0 + ch * 8);
        }
        cp_commit();
    };

    load_stage(0, 0);
    for (int it = 0; it < NIT; it++) {
        int s = it & 1;
        cp_wait<0>();
        __syncthreads();
        if (it + 1 < NIT) load_stage(it + 1, s ^ 1);

        uint32_t da = sA0 + s * TILE_B;
        uint32_t db = sB0 + s * TILE_B;
#pragma unroll
        for (int ks = 0; ks < 32; ks += 16) {
            uint32_t af[4][4], bq[4][4];
#pragma unroll
            for (int mt = 0; mt < 4; mt++)
                ldsm4(af[mt], da + (uint32_t)((wm * 64 + mt * 16 + (lane & 15)) * 80
                                              + (ks + ((lane >> 4) << 3)) * 2));
#pragma unroll
            for (int np = 0; np < 4; np++)
                ldsm4(bq[np], db + (uint32_t)((wn * 64 + np * 16 + (lane & 7) + ((lane >> 4) << 3)) * 80
                                              + (ks + (((lane >> 3) & 1) << 3)) * 2));
#pragma unroll
            for (int mt = 0; mt < 4; mt++)
#pragma unroll
                for (int nt = 0; nt < 8; nt++)
                    mma16816(acc[mt][nt], af[mt], &bq[nt >> 1][(nt & 1) * 2]);
        }
    }

    // ---------------- epilogue ----------------
    int rbase = m0 + wm * 64 + (lane >> 2);
    int cbase = n0 + wn * 64 + (lane & 3) * 2;
    if (MODE == 0) {
#pragma unroll
        for (int mt = 0; mt < 4; mt++)
#pragma unroll
            for (int nt = 0; nt < 8; nt++) {
                int r0 = rbase + mt * 16, c0 = cbase + nt * 8;
                *(float2*)(g_logits + (size_t)r0 * NCODES + c0)       = make_float2(acc[mt][nt][0], acc[mt][nt][1]);
                *(float2*)(g_logits + (size_t)(r0 + 8) * NCODES + c0) = make_float2(acc[mt][nt][2], acc[mt][nt][3]);
            }
    } else {
        float sse = 0.f;
#pragma unroll
        for (int mt = 0; mt < 4; mt++)
#pragma unroll
            for (int nt = 0; nt < 8; nt++) {
                int r0 = rbase + mt * 16, c0 = cbase + nt * 8;
#pragma unroll
                for (int h = 0; h < 2; h++) {
                    size_t o = (size_t)(r0 + h * 8) * KDIM + c0;
                    float2 zv = *(const float2*)(Z + o);
                    float dx = acc[mt][nt][h * 2]     - zv.x;
                    float dy = acc[mt][nt][h * 2 + 1] - zv.y;
                    sse += dx * dx + dy * dy;
                    *(float2*)(Out + o) = make_float2(zv.x + dx, zv.y + dy);
                }
            }
#pragma unroll
        for (int o = 16; o; o >>= 1) sse += __shfl_xor_sync(0xffffffffu, sse, o);
        if (lane == 0) ssum[wid] = sse;
        __syncthreads();
        if (tid == 0)
            g_sse[blockIdx.y * 2 + blockIdx.x] = ssum[0] + ssum[1] + ssum[2] + ssum[3];
    }
}

// ---------------- rowops (32KB smem: only y cached) -------------------------
__global__ __launch_bounds__(256) void rowops(float* __restrict__ outCodes) {
    extern __shared__ float sy[];
    __shared__ float scv[8];
    __shared__ int   sci[8];

    int r = blockIdx.x;
    const float* L = g_logits + (size_t)r * NCODES;

    float av = -3.4e38f; int ai = 0;
    float my = -3.4e38f;
    uint32_t jb = (uint32_t)r * (uint32_t)NCODES;
    for (int c = threadIdx.x; c < NCODES; c += 256) {
        float l = L[c];
        float y = l + gumbel_at(jb + (uint32_t)c);
        sy[c] = y;
        if (l > av) { av = l; ai = c; }
        my = fmaxf(my, y);
    }
    __syncthreads();

    float ML = av; int code = ai;
    blockArgmax(ML, code, scv, sci);
    float MY = blockMax(my, scv);

    float sE = 0.f, sEl = 0.f, sEy = 0.f;
    for (int c = threadIdx.x; c < NCODES; c += 256) {
        float l = L[c];
        float e = __expf(l - ML);
        sE += e; sEl += e * l;
        sEy += __expf(sy[c] - MY);
    }
    float SE  = blockSum(sE, scv);
    float SEl = blockSum(sEl, scv);
    float SY  = blockSum(sEy, scv);

    float inv = 1.0f / SY;
    fp16* wh = g_Whi + (size_t)r * NCODES;
    fp16* wl = g_Wlo + (size_t)r * NCODES;
    for (int c = threadIdx.x; c < NCODES; c += 256) {
        float w = __expf(sy[c] - MY) * inv;
        fp16 h = __float2half_rn(w);
        wh[c] = h;
        wl[c] = __float2half_rn(w - __half2float(h));
    }
    if (threadIdx.x == 0) {
        g_kl[r] = SEl / SE - ML - __logf(SE) + 9.0109131f;   // + ln(8192)
        outCodes[r] = (float)code;
    }
}

// ---------------- finalize --------------------------------------------------
__global__ __launch_bounds__(256) void finalize(float* __restrict__ outLoss) {
    __shared__ float sc[8];
    float k = 0.f;
    for (int i = threadIdx.x; i < NROWS; i += 256) k += g_kl[i];
    float K = blockSum(k, sc);
    float E = blockSum(g_sse[threadIdx.x], sc);
    if (threadIdx.x == 0)
        outLoss[0] = 0.25f * (E / (float)ZELEMS) + 0.01f * (K / (float)NROWS);
}

// ---------------- launch ----------------------------------------------------
extern "C" void kernel_launch(void* const* d_in, const int* in_sizes, int n_in,
                              void* d_out, int out_size) {
    const float* z  = (const float*)d_in[0];
    const float* cb = (const float*)d_in[1];
    float* out = (float*)d_out;
    float* outZ     = out;
    float* outLoss  = out + ZELEMS;
    float* outCodes = out + ZELEMS + 1;

    split_z<<<ZELEMS / 256, 256>>>(z);
    dim3 gs(NCODES / 64, KDIM / 64);
    split_cb<<<gs, 256>>>(cb);

    dim3 g1(NCODES / 128, NROWS / 128);          // (64, 128)
    gemm_mma<0><<<g1, 128>>>(nullptr, nullptr);

    rowops<<<NROWS, 256, NCODES * 4>>>(outCodes);

    dim3 g2(KDIM / 128, NROWS / 128);            // (2, 128)
    gemm_mma<1><<<g2, 128>>>(z, outZ);

    finalize<<<1, 256>>>(outLoss);
}